// round 3
// baseline (speedup 1.0000x reference)
#include <cuda_runtime.h>

#define BB 8
#define CC 512
#define TT 8192
#define OPT 8               // outputs per thread
#define NT 256              // threads per block
#define CHUNK (NT * OPT)    // 2048 outputs per block
#define NCHUNK (TT / CHUNK) // 4 blocks per (b,c) row
#define NPAIR 2053          // z-pairs needed per block: k in [ob-2, ob+2050]
#define SZN 2310            // padded smem slots: idx(2052)=2308

typedef unsigned long long u64;

__device__ __forceinline__ u64 pk2(float lo, float hi) {
    u64 r; asm("mov.b64 %0, {%1, %2};" : "=l"(r) : "f"(lo), "f"(hi)); return r;
}
__device__ __forceinline__ void upk2(u64 v, float& lo, float& hi) {
    asm("mov.b64 {%0, %1}, %2;" : "=f"(lo), "=f"(hi) : "l"(v));
}
__device__ __forceinline__ u64 fma2(u64 a, u64 b, u64 c) {
    u64 d; asm("fma.rn.f32x2 %0, %1, %2, %3;" : "=l"(d) : "l"(a), "l"(b), "l"(c)); return d;
}
__device__ __forceinline__ u64 mul2(u64 a, u64 b) {
    u64 d; asm("mul.rn.f32x2 %0, %1, %2;" : "=l"(d) : "l"(a), "l"(b)); return d;
}

// padded smem index: one pad slot after every 8 pairs -> 72B lane stride, conflict-free
__device__ __forceinline__ int zidx(int L) { return L + (L >> 3); }

__global__ __launch_bounds__(NT) void aa_fused_kernel(
    const float* __restrict__ x,
    const float* __restrict__ alpha,
    const float* __restrict__ beta,
    const float* __restrict__ fu,
    const float* __restrict__ fd,
    float* __restrict__ out)
{
    __shared__ u64 s_z[SZN];
    __shared__ float s_g0[6], s_g1[6], s_fd[12];
    __shared__ float s_a, s_ib;

    const int tid = threadIdx.x;
    const int bid = blockIdx.x;
    const int row = bid >> 2;      // NCHUNK == 4
    const int chunk = bid & 3;
    const int c = row & (CC - 1);

    // Stage filters (2x upsample gain folded in) + per-channel snake params.
    if (tid < 6)        s_g0[tid] = 2.0f * fu[10 - 2 * tid];                   // odd-n phase
    else if (tid < 12)  { int r = tid - 6; s_g1[r] = 2.0f * fu[11 - 2 * r]; }  // even-n phase
    else if (tid < 24)  s_fd[tid - 12] = fd[tid - 12];
    else if (tid == 24) s_a  = expf(alpha[c]);
    else if (tid == 25) s_ib = 1.0f / (expf(beta[c]) + 1e-9f);
    __syncthreads();

    const float a  = s_a;
    const float ib = s_ib;
    const u64 a2  = pk2(a, a);
    const u64 ib2 = pk2(ib, ib);

    // Packed up-filter taps: lane0 = g0 (odd n = 2k-1), lane1 = g1 (even n = 2k).
    // Both phases of pair k read the SAME window x[k-3 .. k+2].
    u64 g2[6];
    #pragma unroll
    for (int r = 0; r < 6; r++) g2[r] = pk2(s_g0[r], s_g1[r]);

    const float* xrow = x + (size_t)row * TT;
    float* orow = out + (size_t)row * TT;
    const int ob = chunk * CHUNK;      // block's first output index

    // Scalar clamped z evaluator (edges + extras only).
    auto zval = [&](int n) -> float {
        n = min(max(n, 0), 2 * TT - 1);
        const int m = n >> 1;
        float acc = 0.0f;
        if (n & 1) {
            #pragma unroll
            for (int r = 0; r < 6; r++) {
                const int j = min(max(m - 2 + r, 0), TT - 1);
                acc += s_g0[r] * __ldg(&xrow[j]);
            }
        } else {
            #pragma unroll
            for (int r = 0; r < 6; r++) {
                const int j = min(max(m - 3 + r, 0), TT - 1);
                acc += s_g1[r] * __ldg(&xrow[j]);
            }
        }
        const float sv = __sinf(acc * a);
        return acc + sv * sv * ib;
    };

    // ---------- Phase 1: each z computed exactly once, stored to smem ----------
    // Thread t produces pairs k = (ob-2) + 8t + j, j=0..7 (local L = 8t+j).
    {
        const int k0 = ob - 2 + tid * OPT;
        const int xbase = ob + tid * OPT - 8;           // aligned float4 base; window offset 3
        const bool fast = (xbase >= 0) && (xbase + 16 <= TT);
        if (fast) {
            u64 xb[16];                                  // broadcast pairs of x[xbase+i]
            const float4* xv = (const float4*)(xrow + xbase);
            #pragma unroll
            for (int i = 0; i < 4; i++) {
                float4 v = xv[i];
                xb[4 * i + 0] = pk2(v.x, v.x); xb[4 * i + 1] = pk2(v.y, v.y);
                xb[4 * i + 2] = pk2(v.z, v.z); xb[4 * i + 3] = pk2(v.w, v.w);
            }
            #pragma unroll
            for (int j = 0; j < OPT; j++) {
                // pair k = k0+j: window xb[3+j .. 8+j]
                u64 acc = mul2(g2[0], xb[3 + j]);
                #pragma unroll
                for (int r = 1; r < 6; r++) acc = fma2(g2[r], xb[3 + j + r], acc);
                float t0, t1; upk2(mul2(acc, a2), t0, t1);
                u64 s2 = pk2(__sinf(t0), __sinf(t1));
                s_z[zidx(tid * OPT + j)] = fma2(mul2(s2, s2), ib2, acc);
            }
        } else {
            #pragma unroll
            for (int j = 0; j < OPT; j++) {
                const int k = k0 + j;
                s_z[zidx(tid * OPT + j)] = pk2(zval(2 * k - 1), zval(2 * k));
            }
        }
        // Extras: 5 tail pairs L = 2048..2052 (k = ob+2046 .. ob+2050)
        if (tid >= NT - 5) {
            const int e = tid - (NT - 5);
            const int k = ob + 2046 + e;
            s_z[zidx(2048 + e)] = pk2(zval(2 * k - 1), zval(2 * k));
        }
    }
    __syncthreads();

    // ---------- Phase 2: downsample from smem ----------
    // out[m] = sum_{u=0..5} (fd[2u], fd[2u+1]) .* zq[m-2+u], then horizontal add.
    u64 fd2[6];
    #pragma unroll
    for (int u = 0; u < 6; u++) fd2[u] = pk2(s_fd[2 * u], s_fd[2 * u + 1]);

    u64 zin[13];
    #pragma unroll
    for (int j = 0; j < 13; j++) zin[j] = s_z[zidx(tid * OPT + j)];

    float o[OPT];
    #pragma unroll
    for (int i = 0; i < OPT; i++) {
        u64 acc = mul2(fd2[0], zin[i]);
        #pragma unroll
        for (int u = 1; u < 6; u++) acc = fma2(fd2[u], zin[i + u], acc);
        float lo, hi; upk2(acc, lo, hi);
        o[i] = lo + hi;
    }
    float4* ov = (float4*)(orow + ob + tid * OPT);
    ov[0] = make_float4(o[0], o[1], o[2], o[3]);
    ov[1] = make_float4(o[4], o[5], o[6], o[7]);
}

extern "C" void kernel_launch(void* const* d_in, const int* in_sizes, int n_in,
                              void* d_out, int out_size)
{
    const float* x     = (const float*)d_in[0];
    const float* alpha = (const float*)d_in[1];
    const float* beta  = (const float*)d_in[2];
    const float* fu    = (const float*)d_in[3];
    const float* fd    = (const float*)d_in[4];
    float* out = (float*)d_out;

    const int grid = BB * CC * NCHUNK; // 16384
    aa_fused_kernel<<<grid, NT>>>(x, alpha, beta, fu, fd, out);
}